// round 6
// baseline (speedup 1.0000x reference)
#include <cuda_runtime.h>
#include <cuda_bf16.h>
#include <math.h>

#define NTOK 1024
#define NEXP 16
#define HDIM 1024
#define DDIM 2048
#define RDIM 16
#define NP   2048          // (token, k) pairs
#define UPW  2048          // 2*H
#define SCALE 0.25f

// -------- device scratch: referenced ONLY from device code (never as host-side args;
// on GB300/ATS the host shadow is silently writable and that bug cost rounds 1-5) ----
__device__ int   g_setupdone;
__device__ int   g_bindfail;
__device__ int   g_isbf16;
__device__ int   g_ids[NP];
__device__ float g_tw[NP];
__device__ int   g_off[NEXP + 1];
__device__ int   g_pairs[NP];
__device__ float g_t[NP * RDIM];
__device__ float g_t2[NP * RDIM];
__device__ float g_up[(size_t)NP * UPW];
__device__ float g_act[(size_t)NP * HDIM];
__device__ float g_down[(size_t)NP * DDIM];

// -------- typed load helpers --------
__device__ __forceinline__ float4 ld4f(const float* p) { return *(const float4*)p; }
__device__ __forceinline__ float4 ld4f(const __nv_bfloat16* p) {
    __nv_bfloat162 a = *(const __nv_bfloat162*)p;
    __nv_bfloat162 b = *(const __nv_bfloat162*)(p + 2);
    float2 fa = __bfloat1622float2(a), fb = __bfloat1622float2(b);
    return make_float4(fa.x, fa.y, fb.x, fb.y);
}
__device__ __forceinline__ float ld1f(const float* p) { return *p; }
__device__ __forceinline__ float ld1f(const __nv_bfloat16* p) { return __bfloat162float(*p); }
template <class T> struct IsBF { static const int v = 0; };
template <> struct IsBF<__nv_bfloat16> { static const int v = 1; };

// -------- setup: dtype probes, id/weight identification, grouping --------
__global__ __launch_bounds__(256) void setup_kernel(const unsigned* __restrict__ wup_raw,
                                                    const unsigned* __restrict__ cA,
                                                    const unsigned* __restrict__ cB) {
    __shared__ int saneW;
    __shared__ int wf32[2], wbf[2];
    __shared__ int idu[2], idl[2], idf[2];
    __shared__ int cnt[NEXP], cur[NEXP];
    __shared__ int idsc, twc, idsmode, twmode;
    int tid = threadIdx.x;
    if (tid == 0) saneW = 0;
    if (tid < 2) { wf32[tid] = 0; wbf[tid] = 0; idu[tid] = 0; idl[tid] = 0; idf[tid] = 0; }
    if (tid < NEXP) cnt[tid] = 0;
    __syncthreads();

    int s = 0;
    for (int i = tid; i < 4096; i += 256) {
        unsigned ex = (wup_raw[i] >> 7) & 0xFFu;
        if (ex >= 100 && ex <= 130) s++;
    }
    atomicAdd(&saneW, s);

    for (int c = 0; c < 2; c++) {
        const unsigned* X = c ? cB : cA;
        int sf = 0, sb = 0, bu = 0, bl = 0, bf = 0;
        for (int t = tid; t < 512; t += 256) {
            unsigned w0 = X[2 * t], w1 = X[2 * t + 1];
            float a = __uint_as_float(w0), b = __uint_as_float(w1);
            if (fabsf(a + b - 1.0f) < 0.02f) sf++;
            float ba = __bfloat162float(((const __nv_bfloat16*)X)[2 * t]);
            float bb = __bfloat162float(((const __nv_bfloat16*)X)[2 * t + 1]);
            if (fabsf(ba + bb - 1.0f) < 0.05f) sb++;
            if (w0 >= NEXP || w1 >= NEXP) bu = 1;
            if (w0 >= NEXP || w1 != 0) bl = 1;
            if (!(a >= 0.f && a < (float)NEXP && a == floorf(a)) ||
                !(b >= 0.f && b < (float)NEXP && b == floorf(b))) bf = 1;
        }
        atomicAdd(&wf32[c], sf); atomicAdd(&wbf[c], sb);
        if (bu) atomicExch(&idu[c], 1);
        if (bl) atomicExch(&idl[c], 1);
        if (bf) atomicExch(&idf[c], 1);
    }
    __syncthreads();

    if (tid == 0) {
        int wmode[2], imode[2];
        for (int c = 0; c < 2; c++) {
            wmode[c] = (wf32[c] > 480) ? 1 : ((wbf[c] > 480) ? 2 : 0);
            imode[c] = (!idl[c]) ? 2 : ((!idu[c]) ? 1 : ((!idf[c]) ? 3 : 0));
        }
        int ic = -1, wc = -1;
        if (imode[0] && wmode[1]) { ic = 0; wc = 1; }
        else if (imode[1] && wmode[0]) { ic = 1; wc = 0; }
        g_bindfail = (ic < 0) ? 1 : 0;
        idsc = (ic < 0) ? 0 : ic;
        twc  = (ic < 0) ? 1 : wc;
        idsmode = imode[idsc] ? imode[idsc] : 1;
        twmode  = wmode[twc] ? wmode[twc] : 1;
        g_isbf16 = (saneW > 2048) ? 1 : 0;
    }
    __syncthreads();

    const unsigned* idsbuf = idsc ? cB : cA;
    const unsigned* twbuf  = twc  ? cB : cA;
    int im = idsmode, tm = twmode;
    for (int p = tid; p < NP; p += 256) {
        int id;
        if (im == 2)      id = (int)idsbuf[2 * p];
        else if (im == 3) id = (int)__uint_as_float(idsbuf[p]);
        else              id = (int)idsbuf[p];
        g_ids[p] = id & (NEXP - 1);
        g_tw[p] = (tm == 2) ? __bfloat162float(((const __nv_bfloat16*)twbuf)[p])
                            : __uint_as_float(twbuf[p]);
    }
    __syncthreads();

    for (int p = tid; p < NP; p += 256) atomicAdd(&cnt[g_ids[p]], 1);
    __syncthreads();
    if (tid == 0) {
        int a = 0;
        for (int e = 0; e < NEXP; e++) { g_off[e] = a; a += cnt[e]; }
        g_off[NEXP] = a;
    }
    __syncthreads();
    if (tid < NEXP) cur[tid] = g_off[tid];
    __syncthreads();
    for (int p = tid; p < NP; p += 256) {
        int pos = atomicAdd(&cur[g_ids[p]], 1);
        g_pairs[pos & (NP - 1)] = p;
    }
    __syncthreads();
    if (tid == 0) g_setupdone = 1;
}

// -------- seeds (diagnostic sentinels, overwritten by healthy pipeline) --------
__global__ __launch_bounds__(256) void seed_kernel(void* __restrict__ outv) {
    int i = blockIdx.x * blockDim.x + threadIdx.x;
    if (i == 0) { g_t[0] = 777.0f; g_t2[0] = 777.0f; }
    if (i < 256) { g_up[i] = 12345.0f; g_down[i] = 0.125f; }
    if (i < NTOK * DDIM) {
        if (g_isbf16) ((__nv_bfloat16*)outv)[i] = __float2bfloat16(0.5f);
        else          ((float*)outv)[i] = 0.5f;
    }
}

// -------- LoRA-A GEMV --------
// DOWN=0: X=hidden (arg), row=p>>1, writes g_t.  DOWN=1: X=g_act, row=p, writes g_t2.
template <bool DOWN, class TA>
__global__ __launch_bounds__(256) void lora_t_kernel(const void* __restrict__ Xv,
                                                     const TA* __restrict__ A, int Dlen) {
    if (g_isbf16 != IsBF<TA>::v) return;
    int p = blockIdx.x;
    int e = g_ids[p];
    float* T = DOWN ? g_t2 : g_t;
    int warp = threadIdx.x >> 5, lane = threadIdx.x & 31;
    for (int r = warp; r < RDIM; r += 8) {
        const TA* a = A + ((size_t)e * RDIM + r) * Dlen;
        float s = 0.f;
        for (int i = lane * 4; i < Dlen; i += 128) {
            float4 xv;
            if (DOWN) xv = ld4f(g_act + (size_t)p * Dlen + i);
            else      xv = ld4f((const TA*)Xv + (size_t)(p >> 1) * Dlen + i);
            float4 av = ld4f(a + i);
            s += xv.x * av.x + xv.y * av.y + xv.z * av.z + xv.w * av.w;
        }
        #pragma unroll
        for (int o = 16; o; o >>= 1) s += __shfl_xor_sync(0xffffffffu, s, o);
        if (lane == 0) T[p * RDIM + r] = s;
    }
}

// -------- expert-grouped GEMM with fused LoRA-B epilogue --------
#define BM 64
#define BN 64
#define BK 16

template <bool IS_DOWN, class TW>
__global__ __launch_bounds__(256) void moe_gemm(const void* __restrict__ Av,  // hidden (up only)
                                                const TW* __restrict__ W,
                                                const TW* __restrict__ LB,
                                                int Kd, int Ncols) {
    if (g_isbf16 != IsBF<TW>::v) return;
    const float* T = IS_DOWN ? g_t2 : g_t;
    float* Out = IS_DOWN ? g_down : g_up;

    int e = blockIdx.z;
    int mstart = g_off[e] + blockIdx.y * BM;
    int mend = g_off[e + 1];
    if (mstart >= mend) return;
    int mv = min(BM, mend - mstart);
    int o0 = blockIdx.x * BN;

    __shared__ float As[BK][BM];
    __shared__ float Bs[BK][BN];
    __shared__ int   Pr[BM];
    __shared__ float Ts[BM][RDIM + 1];
    __shared__ float Us[BN][RDIM + 1];

    int tid = threadIdx.x;
    if (tid < BM) Pr[tid] = g_pairs[((tid < mv) ? (mstart + tid) : mstart) & (NP - 1)] & (NP - 1);
    __syncthreads();

    int tx = tid & 15, ty = tid >> 4;
    int lrow = tid >> 2;
    int lc4  = (tid & 3) * 4;

    int prow = Pr[lrow];
    int arow = IS_DOWN ? prow : (prow >> 1);
    const TW* bptr = W + ((size_t)e * Ncols + o0 + lrow) * Kd;

    float acc[4][4] = {};

    for (int k0 = 0; k0 < Kd; k0 += BK) {
        float4 av;
        if (IS_DOWN) av = ld4f(g_act + (size_t)arow * Kd + k0 + lc4);
        else         av = ld4f((const TW*)Av + (size_t)arow * Kd + k0 + lc4);
        float4 bv = ld4f(bptr + k0 + lc4);
        __syncthreads();
        As[lc4 + 0][lrow] = av.x; As[lc4 + 1][lrow] = av.y;
        As[lc4 + 2][lrow] = av.z; As[lc4 + 3][lrow] = av.w;
        Bs[lc4 + 0][lrow] = bv.x; Bs[lc4 + 1][lrow] = bv.y;
        Bs[lc4 + 2][lrow] = bv.z; Bs[lc4 + 3][lrow] = bv.w;
        __syncthreads();
        #pragma unroll
        for (int kk = 0; kk < BK; kk++) {
            float4 a = *(const float4*)&As[kk][ty * 4];
            float4 b = *(const float4*)&Bs[kk][tx * 4];
            acc[0][0] += a.x * b.x; acc[0][1] += a.x * b.y; acc[0][2] += a.x * b.z; acc[0][3] += a.x * b.w;
            acc[1][0] += a.y * b.x; acc[1][1] += a.y * b.y; acc[1][2] += a.y * b.z; acc[1][3] += a.y * b.w;
            acc[2][0] += a.z * b.x; acc[2][1] += a.z * b.y; acc[2][2] += a.z * b.z; acc[2][3] += a.z * b.w;
            acc[3][0] += a.w * b.x; acc[3][1] += a.w * b.y; acc[3][2] += a.w * b.z; acc[3][3] += a.w * b.w;
        }
    }

    __syncthreads();
    for (int i = tid; i < BM * RDIM; i += 256) {
        int m = i >> 4, r = i & 15;
        Ts[m][r] = T[Pr[m] * RDIM + r];
    }
    for (int i = tid; i < BN * RDIM; i += 256) {
        int n = i >> 4, r = i & 15;
        Us[n][r] = ld1f(LB + ((size_t)e * Ncols + o0 + n) * RDIM + r);
    }
    __syncthreads();

    #pragma unroll
    for (int i = 0; i < 4; i++) {
        int m = ty * 4 + i;
        if (m >= mv) continue;
        int p = Pr[m];
        float w = IS_DOWN ? g_tw[p] : 1.0f;
        #pragma unroll
        for (int j = 0; j < 4; j++) {
            int n = tx * 4 + j;
            float l = 0.f;
            #pragma unroll
            for (int r = 0; r < RDIM; r++) l += Ts[m][r] * Us[n][r];
            float v = acc[i][j] + SCALE * l;
            if (IS_DOWN) v *= w;
            Out[(size_t)p * Ncols + o0 + n] = v;
        }
    }
}

// -------- gelu(up[:H]) * up[H:] --------
__global__ __launch_bounds__(256) void act_kernel() {
    int i = blockIdx.x * blockDim.x + threadIdx.x;
    if (i >= NP * HDIM) return;
    int p = i >> 10, h = i & (HDIM - 1);
    float a = g_up[(size_t)p * UPW + h];
    float b = g_up[(size_t)p * UPW + HDIM + h];
    float ge = 0.5f * a * (1.0f + erff(a * 0.70710678118654752f));
    g_act[(size_t)p * HDIM + h] = ge * b;
}

// -------- combine + verdict --------
__global__ __launch_bounds__(256) void combine_verdict(void* __restrict__ outv) {
    int code = 0;
    if (!g_setupdone)               code = 1;   // rel ~3.8
    else if (g_bindfail)            code = 2;   // rel ~7.4
    else if (g_off[NEXP] != NP)     code = 4;   // rel ~14.8
    else if (g_t[0] == 777.0f)      code = 3;   // rel ~11.1 (up-LoRA never wrote)
    else if (g_up[0] == 12345.0f)   code = 8;   // rel ~29.6 (up GEMM never wrote)
    else if (g_t2[0] == 777.0f)     code = 5;   // rel ~18.5 (down-LoRA never wrote)
    else if (g_down[0] == 0.125f)   code = 16;  // rel ~59  (down GEMM never wrote)
    int i = blockIdx.x * blockDim.x + threadIdx.x;
    if (i >= NTOK * DDIM) return;
    float v;
    if (code) v = (float)code;
    else {
        int n = i >> 11, d = i & (DDIM - 1);
        v = g_down[(size_t)(2 * n) * DDIM + d] + g_down[(size_t)(2 * n + 1) * DDIM + d];
    }
    if (g_isbf16) ((__nv_bfloat16*)outv)[i] = __float2bfloat16(v);
    else          ((float*)outv)[i] = v;
}

typedef __nv_bfloat16 bf16;

extern "C" void kernel_launch(void* const* d_in, const int* in_sizes, int n_in,
                              void* d_out, int out_size) {
    long long mx = 0;
    for (int i = 0; i < n_in; i++) if ((long long)in_sizes[i] > mx) mx = in_sizes[i];
    int div = 1;
    if (mx == 268435456LL) div = 4;
    else if (mx == 134217728LL) div = 2;

    int idx_hidden = -1, idx_wup = -1, idx_wdown = -1, idx_downa = -1;
    int idxc[2] = {-1, -1}; int nc = 0;
    int idx512k[3] = {-1, -1, -1}; int n512k = 0;
    for (int i = 0; i < n_in; i++) {
        long long es = (long long)in_sizes[i] / div;
        if      (es == 2097152)  idx_hidden = i;
        else if (es == 67108864) idx_wup = i;
        else if (es == 33554432) idx_wdown = i;
        else if (es == 262144)   idx_downa = i;
        else if (es == 2048 || (div == 2 && es == 4096)) { if (nc < 2) idxc[nc++] = i; }
        else if (es == 524288)   { if (n512k < 3) idx512k[n512k++] = i; }
    }

    int idx_upa = -1, idx_upb = -1, idx_downb = -1;
    bool ok = (idx_hidden >= 0 && idx_wup >= 0 && idx_wdown >= 0 && idx_downa >= 0 &&
               nc == 2 && n512k == 3);
    if (ok) {
        if (idx_downa < idx512k[0]) { idx_downb = idx512k[0]; idx_upa = idx512k[1]; idx_upb = idx512k[2]; }
        else                        { idx_upa = idx512k[0]; idx_upb = idx512k[1]; idx_downb = idx512k[2]; }
    } else if (n_in >= 9) {
        idx_hidden = 0; idxc[0] = 1; idxc[1] = 2; idx_wup = 3; idx_wdown = 4;
        idx_upa = 5; idx_upb = 6; idx_downa = 7; idx_downb = 8;
    } else {
        return;
    }

    const void* hidden = d_in[idx_hidden];
    const void* w_up   = d_in[idx_wup];
    const void* w_down = d_in[idx_wdown];
    const void* up_a   = d_in[idx_upa];
    const void* up_b   = d_in[idx_upb];
    const void* down_a = d_in[idx_downa];
    const void* down_b = d_in[idx_downb];

    setup_kernel<<<1, 256>>>((const unsigned*)w_up, (const unsigned*)d_in[idxc[0]],
                             (const unsigned*)d_in[idxc[1]]);
    seed_kernel<<<(NTOK * DDIM + 255) / 256, 256>>>(d_out);

    lora_t_kernel<false, float><<<NP, 256>>>(hidden, (const float*)up_a, DDIM);
    lora_t_kernel<false, bf16><<<NP, 256>>>(hidden, (const bf16*)up_a, DDIM);

    {
        dim3 grid(UPW / BN, (NP + BM - 1) / BM, NEXP);
        moe_gemm<false, float><<<grid, 256>>>(hidden, (const float*)w_up, (const float*)up_b, DDIM, UPW);
        moe_gemm<false, bf16><<<grid, 256>>>(hidden, (const bf16*)w_up, (const bf16*)up_b, DDIM, UPW);
    }

    act_kernel<<<(NP * HDIM + 255) / 256, 256>>>();

    lora_t_kernel<true, float><<<NP, 256>>>(nullptr, (const float*)down_a, HDIM);
    lora_t_kernel<true, bf16><<<NP, 256>>>(nullptr, (const bf16*)down_a, HDIM);

    {
        dim3 grid(DDIM / BN, (NP + BM - 1) / BM, NEXP);
        moe_gemm<true, float><<<grid, 256>>>(nullptr, (const float*)w_down, (const float*)down_b, HDIM, DDIM);
        moe_gemm<true, bf16><<<grid, 256>>>(nullptr, (const bf16*)w_down, (const bf16*)down_b, HDIM, DDIM);
    }

    combine_verdict<<<(NTOK * DDIM + 255) / 256, 256>>>(d_out);
}

// round 7
// speedup vs baseline: 1.4034x; 1.4034x over previous
#include <cuda_runtime.h>
#include <cuda_bf16.h>
#include <math.h>

#define NTOK 1024
#define NEXP 16
#define HDIM 1024
#define DDIM 2048
#define RDIM 16
#define NP   2048          // (token, k) pairs
#define UPW  2048          // 2*H
#define SCALE 0.25f

// -------- device scratch: referenced ONLY from device code (GB300/ATS host-shadow trap) --
__device__ int   g_setupdone;
__device__ int   g_bindfail;
__device__ int   g_ids[NP];
__device__ float g_tw[NP];
__device__ int   g_off[NEXP + 1];
__device__ int   g_pairs[NP];
__device__ float g_t[NP * RDIM];
__device__ float g_t2[NP * RDIM];
__device__ float g_up[(size_t)NP * UPW];
__device__ float g_act[(size_t)NP * HDIM];
__device__ float g_down[(size_t)NP * DDIM];

__device__ __forceinline__ unsigned f2tf(float f) {
    unsigned u;
    asm("cvt.rna.tf32.f32 %0, %1;" : "=r"(u) : "f"(f));
    return u;
}
// permuted k offset: puts (k, k+4) adjacent for LDS.64 fragment loads
__device__ __forceinline__ int koff(int k) {
    return (k & ~7) + ((k & 3) * 2) + ((k >> 2) & 1);
}

// -------- setup: semantic id/weight identification + expert grouping --------
__global__ __launch_bounds__(256) void setup_kernel(const unsigned* __restrict__ cA,
                                                    const unsigned* __restrict__ cB) {
    __shared__ int wf32[2];
    __shared__ int idu[2], idl[2], idf[2];
    __shared__ int cnt[NEXP], cur[NEXP];
    __shared__ int idsc, idsmode;
    int tid = threadIdx.x;
    if (tid < 2) { wf32[tid] = 0; idu[tid] = 0; idl[tid] = 0; idf[tid] = 0; }
    if (tid < NEXP) cnt[tid] = 0;
    __syncthreads();

    for (int c = 0; c < 2; c++) {
        const unsigned* X = c ? cB : cA;
        int sf = 0, bu = 0, bl = 0, bf = 0;
        for (int t = tid; t < 512; t += 256) {
            unsigned w0 = X[2 * t], w1 = X[2 * t + 1];
            float a = __uint_as_float(w0), b = __uint_as_float(w1);
            if (fabsf(a + b - 1.0f) < 0.02f) sf++;
            if (w0 >= NEXP || w1 >= NEXP) bu = 1;
            if (w0 >= NEXP || w1 != 0) bl = 1;
            if (!(a >= 0.f && a < (float)NEXP && a == floorf(a)) ||
                !(b >= 0.f && b < (float)NEXP && b == floorf(b))) bf = 1;
        }
        atomicAdd(&wf32[c], sf);
        if (bu) atomicExch(&idu[c], 1);
        if (bl) atomicExch(&idl[c], 1);
        if (bf) atomicExch(&idf[c], 1);
    }
    __syncthreads();

    if (tid == 0) {
        int wmode[2], imode[2];
        for (int c = 0; c < 2; c++) {
            wmode[c] = (wf32[c] > 480) ? 1 : 0;
            imode[c] = (!idl[c]) ? 2 : ((!idu[c]) ? 1 : ((!idf[c]) ? 3 : 0));
        }
        int ic = -1;
        if (imode[0] && wmode[1]) ic = 0;
        else if (imode[1] && wmode[0]) ic = 1;
        g_bindfail = (ic < 0) ? 1 : 0;
        idsc = (ic < 0) ? 0 : ic;
        idsmode = imode[idsc] ? imode[idsc] : 1;
    }
    __syncthreads();

    const unsigned* idsbuf = idsc ? cB : cA;
    const unsigned* twbuf  = idsc ? cA : cB;
    int im = idsmode;
    for (int p = tid; p < NP; p += 256) {
        int id;
        if (im == 2)      id = (int)idsbuf[2 * p];
        else if (im == 3) id = (int)__uint_as_float(idsbuf[p]);
        else              id = (int)idsbuf[p];
        g_ids[p] = id & (NEXP - 1);
        g_tw[p] = __uint_as_float(twbuf[p]);
    }
    __syncthreads();

    for (int p = tid; p < NP; p += 256) atomicAdd(&cnt[g_ids[p]], 1);
    __syncthreads();
    if (tid == 0) {
        int a = 0;
        for (int e = 0; e < NEXP; e++) { g_off[e] = a; a += cnt[e]; }
        g_off[NEXP] = a;
    }
    __syncthreads();
    if (tid < NEXP) cur[tid] = g_off[tid];
    __syncthreads();
    for (int p = tid; p < NP; p += 256) {
        int pos = atomicAdd(&cur[g_ids[p]], 1);
        g_pairs[pos & (NP - 1)] = p;
    }
    __syncthreads();
    if (tid == 0) g_setupdone = 1;
}

// -------- seeds (diagnostic sentinels) --------
__global__ __launch_bounds__(256) void seed_kernel(float* __restrict__ outv) {
    int i = blockIdx.x * blockDim.x + threadIdx.x;
    if (i == 0) { g_t[0] = 777.0f; g_t2[0] = 777.0f; }
    if (i < 256) { g_up[i] = 12345.0f; g_down[i] = 0.125f; }
    if (i < NTOK * DDIM) outv[i] = 0.5f;
}

// -------- LoRA-A GEMV (fp32) --------
template <bool DOWN>
__global__ __launch_bounds__(256) void lora_t_kernel(const float* __restrict__ Xv,
                                                     const float* __restrict__ A, int Dlen) {
    int p = blockIdx.x;
    int e = g_ids[p];
    float* T = DOWN ? g_t2 : g_t;
    int warp = threadIdx.x >> 5, lane = threadIdx.x & 31;
    const float* xrow = DOWN ? (g_act + (size_t)p * Dlen)
                             : (Xv + (size_t)(p >> 1) * Dlen);
    for (int r = warp; r < RDIM; r += 8) {
        const float* a = A + ((size_t)e * RDIM + r) * Dlen;
        float s = 0.f;
        for (int i = lane * 4; i < Dlen; i += 128) {
            float4 xv = *(const float4*)(xrow + i);
            float4 av = *(const float4*)(a + i);
            s += xv.x * av.x + xv.y * av.y + xv.z * av.z + xv.w * av.w;
        }
        #pragma unroll
        for (int o = 16; o; o >>= 1) s += __shfl_xor_sync(0xffffffffu, s, o);
        if (lane == 0) T[p * RDIM + r] = s;
    }
}

// -------- expert-grouped tf32 mma GEMM with LoRA-B folded into the k-loop --------
// Tile: BM=128 x BN=64 x BK=32. 256 thr = 8 warps (4x2), warp tile 32x32,
// mma m16n8k8 tf32. Single SMEM buffer + register prefetch. Stride-40 padding
// gives conflict-free LDS.64 fragment loads of (k, k+4) pairs (permuted layout).
#define BM 128
#define BN 64
#define BK 32
#define LDT 40

template <bool IS_DOWN>
__global__ __launch_bounds__(256) void mma_gemm(const float* __restrict__ Av,  // hidden (up only)
                                                const float* __restrict__ W,   // [E, Ncols, Kd]
                                                const float* __restrict__ LB,  // [E, Ncols, R]
                                                int Kd, int Ncols) {
    int e = blockIdx.z;
    int mstart = g_off[e] + blockIdx.y * BM;
    int mend = g_off[e + 1];
    if (mstart >= mend) return;
    int mv = min(BM, mend - mstart);
    int o0 = blockIdx.x * BN;

    __shared__ __align__(16) unsigned As[BM * LDT];
    __shared__ __align__(16) unsigned Bs[BN * LDT];
    __shared__ int Pr[BM];

    int tid = threadIdx.x;
    int lane = tid & 31, wid = tid >> 5;
    int warp_m = wid >> 1, warp_n = wid & 1;
    int am_base = warp_m * 32;
    int bn_base = warp_n * 32;

    if (tid < BM) Pr[tid] = g_pairs[mstart + ((tid < mv) ? tid : (mv - 1))];
    __syncthreads();

    // ---- loader assignments ----
    int lrow  = tid >> 1;            // A tile row 0..127
    int khalf = (tid & 1) * 16;      // which 16-k half this thread loads
    int brow  = tid >> 2;            // B tile row 0..63
    int kq    = (tid & 3) * 8;       // 8-k quarter

    int prow = Pr[lrow];
    int arow = IS_DOWN ? prow : (prow >> 1);
    const float* abase = IS_DOWN ? (g_act + (size_t)arow * Kd)
                                 : (Av + (size_t)arow * Kd);
    const float* bbase = W + ((size_t)e * Ncols + o0 + brow) * Kd;

    float c[2][4][4];
    #pragma unroll
    for (int i = 0; i < 2; i++)
        #pragma unroll
        for (int j = 0; j < 4; j++)
            #pragma unroll
            for (int q = 0; q < 4; q++) c[i][j][q] = 0.f;

    float4 av[4], bv[2];
    int nch = Kd / BK;

    // prefetch chunk 0
    {
        const float* ap = abase + khalf;
        av[0] = *(const float4*)(ap + 0);  av[1] = *(const float4*)(ap + 4);
        av[2] = *(const float4*)(ap + 8);  av[3] = *(const float4*)(ap + 12);
        const float* bp = bbase + kq;
        bv[0] = *(const float4*)(bp + 0);  bv[1] = *(const float4*)(bp + 4);
    }

    for (int ch = 0; ch < nch; ch++) {
        __syncthreads();
        // store A (cvt to tf32, permuted)
        #pragma unroll
        for (int j = 0; j < 4; j++) {
            int kb = khalf + j * 4;
            float4 v = av[j];
            As[lrow * LDT + koff(kb + 0)] = f2tf(v.x);
            As[lrow * LDT + koff(kb + 1)] = f2tf(v.y);
            As[lrow * LDT + koff(kb + 2)] = f2tf(v.z);
            As[lrow * LDT + koff(kb + 3)] = f2tf(v.w);
        }
        #pragma unroll
        for (int j = 0; j < 2; j++) {
            int kb = kq + j * 4;
            float4 v = bv[j];
            Bs[brow * LDT + koff(kb + 0)] = f2tf(v.x);
            Bs[brow * LDT + koff(kb + 1)] = f2tf(v.y);
            Bs[brow * LDT + koff(kb + 2)] = f2tf(v.z);
            Bs[brow * LDT + koff(kb + 3)] = f2tf(v.w);
        }
        __syncthreads();
        if (ch + 1 < nch) {
            int k0 = (ch + 1) * BK;
            const float* ap = abase + k0 + khalf;
            av[0] = *(const float4*)(ap + 0);  av[1] = *(const float4*)(ap + 4);
            av[2] = *(const float4*)(ap + 8);  av[3] = *(const float4*)(ap + 12);
            const float* bp = bbase + k0 + kq;
            bv[0] = *(const float4*)(bp + 0);  bv[1] = *(const float4*)(bp + 4);
        }
        // compute 4 k-steps of 8
        #pragma unroll
        for (int ks = 0; ks < 4; ks++) {
            int kb = ks * 8 + (lane & 3) * 2;
            uint2 aA[2], aB[2];
            #pragma unroll
            for (int mt = 0; mt < 2; mt++) {
                int r0 = am_base + mt * 16 + (lane >> 2);
                aA[mt] = *(const uint2*)&As[r0 * LDT + kb];
                aB[mt] = *(const uint2*)&As[(r0 + 8) * LDT + kb];
            }
            #pragma unroll
            for (int nt = 0; nt < 4; nt++) {
                int cn = bn_base + nt * 8 + (lane >> 2);
                uint2 bf = *(const uint2*)&Bs[cn * LDT + kb];
                #pragma unroll
                for (int mt = 0; mt < 2; mt++) {
                    asm volatile(
                        "mma.sync.aligned.m16n8k8.row.col.f32.tf32.tf32.f32 "
                        "{%0,%1,%2,%3}, {%4,%5,%6,%7}, {%8,%9}, {%0,%1,%2,%3};"
                        : "+f"(c[mt][nt][0]), "+f"(c[mt][nt][1]),
                          "+f"(c[mt][nt][2]), "+f"(c[mt][nt][3])
                        : "r"(aA[mt].x), "r"(aB[mt].x), "r"(aA[mt].y), "r"(aB[mt].y),
                          "r"(bf.x), "r"(bf.y));
                }
            }
        }
    }

    // ---- LoRA-B extension chunk: A <- SCALE*T[p][r], B <- LB[n][r], K=16 ----
    __syncthreads();
    if ((tid & 1) == 0) {
        int row = tid >> 1;
        const float* tp = (IS_DOWN ? g_t2 : g_t) + Pr[row] * RDIM;
        #pragma unroll
        for (int j = 0; j < 4; j++) {
            float4 v = *(const float4*)(tp + j * 4);
            int kb = j * 4;
            As[row * LDT + koff(kb + 0)] = f2tf(v.x * SCALE);
            As[row * LDT + koff(kb + 1)] = f2tf(v.y * SCALE);
            As[row * LDT + koff(kb + 2)] = f2tf(v.z * SCALE);
            As[row * LDT + koff(kb + 3)] = f2tf(v.w * SCALE);
        }
    }
    if ((tid & 3) < 2) {
        int col = tid >> 2;
        const float* lp = LB + ((size_t)e * Ncols + o0 + col) * RDIM + kq;
        #pragma unroll
        for (int j = 0; j < 2; j++) {
            float4 v = *(const float4*)(lp + j * 4);
            int kb = kq + j * 4;
            Bs[col * LDT + koff(kb + 0)] = f2tf(v.x);
            Bs[col * LDT + koff(kb + 1)] = f2tf(v.y);
            Bs[col * LDT + koff(kb + 2)] = f2tf(v.z);
            Bs[col * LDT + koff(kb + 3)] = f2tf(v.w);
        }
    }
    __syncthreads();
    #pragma unroll
    for (int ks = 0; ks < 2; ks++) {
        int kb = ks * 8 + (lane & 3) * 2;
        uint2 aA[2], aB[2];
        #pragma unroll
        for (int mt = 0; mt < 2; mt++) {
            int r0 = am_base + mt * 16 + (lane >> 2);
            aA[mt] = *(const uint2*)&As[r0 * LDT + kb];
            aB[mt] = *(const uint2*)&As[(r0 + 8) * LDT + kb];
        }
        #pragma unroll
        for (int nt = 0; nt < 4; nt++) {
            int cn = bn_base + nt * 8 + (lane >> 2);
            uint2 bf = *(const uint2*)&Bs[cn * LDT + kb];
            #pragma unroll
            for (int mt = 0; mt < 2; mt++) {
                asm volatile(
                    "mma.sync.aligned.m16n8k8.row.col.f32.tf32.tf32.f32 "
                    "{%0,%1,%2,%3}, {%4,%5,%6,%7}, {%8,%9}, {%0,%1,%2,%3};"
                    : "+f"(c[mt][nt][0]), "+f"(c[mt][nt][1]),
                      "+f"(c[mt][nt][2]), "+f"(c[mt][nt][3])
                    : "r"(aA[mt].x), "r"(aB[mt].x), "r"(aA[mt].y), "r"(aB[mt].y),
                      "r"(bf.x), "r"(bf.y));
            }
        }
    }

    // ---- writeout ----
    float* Out = IS_DOWN ? g_down : g_up;
    #pragma unroll
    for (int mt = 0; mt < 2; mt++) {
        int m0 = am_base + mt * 16 + (lane >> 2);
        #pragma unroll
        for (int half = 0; half < 2; half++) {
            int m = m0 + half * 8;
            if (m >= mv) continue;
            int p = Pr[m];
            float w = IS_DOWN ? g_tw[p] : 1.0f;
            float* op = Out + (size_t)p * Ncols + o0;
            #pragma unroll
            for (int nt = 0; nt < 4; nt++) {
                int n = bn_base + nt * 8 + (lane & 3) * 2;
                float2 v;
                v.x = c[mt][nt][half * 2 + 0];
                v.y = c[mt][nt][half * 2 + 1];
                if (IS_DOWN) { v.x *= w; v.y *= w; }
                *(float2*)&op[n] = v;
            }
        }
    }
}

// -------- gelu(up[:H]) * up[H:] --------
__global__ __launch_bounds__(256) void act_kernel() {
    int i = blockIdx.x * blockDim.x + threadIdx.x;
    if (i >= NP * HDIM) return;
    int p = i >> 10, h = i & (HDIM - 1);
    float a = g_up[(size_t)p * UPW + h];
    float b = g_up[(size_t)p * UPW + HDIM + h];
    float ge = 0.5f * a * (1.0f + erff(a * 0.70710678118654752f));
    g_act[(size_t)p * HDIM + h] = ge * b;
}

// -------- combine + verdict --------
__global__ __launch_bounds__(256) void combine_verdict(float* __restrict__ outv) {
    int code = 0;
    if (!g_setupdone)               code = 1;
    else if (g_bindfail)            code = 2;
    else if (g_off[NEXP] != NP)     code = 4;
    else if (g_t[0] == 777.0f)      code = 3;
    else if (g_up[0] == 12345.0f)   code = 8;
    else if (g_t2[0] == 777.0f)     code = 5;
    else if (g_down[0] == 0.125f)   code = 16;
    int i = blockIdx.x * blockDim.x + threadIdx.x;
    if (i >= NTOK * DDIM) return;
    float v;
    if (code) v = (float)code;
    else {
        int n = i >> 11, d = i & (DDIM - 1);
        v = g_down[(size_t)(2 * n) * DDIM + d] + g_down[(size_t)(2 * n + 1) * DDIM + d];
    }
    outv[i] = v;
}

extern "C" void kernel_launch(void* const* d_in, const int* in_sizes, int n_in,
                              void* d_out, int out_size) {
    long long mx = 0;
    for (int i = 0; i < n_in; i++) if ((long long)in_sizes[i] > mx) mx = in_sizes[i];
    int div = 1;
    if (mx == 268435456LL) div = 4;
    else if (mx == 134217728LL) div = 2;

    int idx_hidden = -1, idx_wup = -1, idx_wdown = -1, idx_downa = -1;
    int idxc[2] = {-1, -1}; int nc = 0;
    int idx512k[3] = {-1, -1, -1}; int n512k = 0;
    for (int i = 0; i < n_in; i++) {
        long long es = (long long)in_sizes[i] / div;
        if      (es == 2097152)  idx_hidden = i;
        else if (es == 67108864) idx_wup = i;
        else if (es == 33554432) idx_wdown = i;
        else if (es == 262144)   idx_downa = i;
        else if (es == 2048 || (div == 2 && es == 4096)) { if (nc < 2) idxc[nc++] = i; }
        else if (es == 524288)   { if (n512k < 3) idx512k[n512k++] = i; }
    }

    int idx_upa = -1, idx_upb = -1, idx_downb = -1;
    bool ok = (idx_hidden >= 0 && idx_wup >= 0 && idx_wdown >= 0 && idx_downa >= 0 &&
               nc == 2 && n512k == 3);
    if (ok) {
        if (idx_downa < idx512k[0]) { idx_downb = idx512k[0]; idx_upa = idx512k[1]; idx_upb = idx512k[2]; }
        else                        { idx_upa = idx512k[0]; idx_upb = idx512k[1]; idx_downb = idx512k[2]; }
    } else if (n_in >= 9) {
        idx_hidden = 0; idxc[0] = 1; idxc[1] = 2; idx_wup = 3; idx_wdown = 4;
        idx_upa = 5; idx_upb = 6; idx_downa = 7; idx_downb = 8;
    } else {
        return;
    }

    const float* hidden = (const float*)d_in[idx_hidden];
    const float* w_up   = (const float*)d_in[idx_wup];
    const float* w_down = (const float*)d_in[idx_wdown];
    const float* up_a   = (const float*)d_in[idx_upa];
    const float* up_b   = (const float*)d_in[idx_upb];
    const float* down_a = (const float*)d_in[idx_downa];
    const float* down_b = (const float*)d_in[idx_downb];
    float* out = (float*)d_out;

    setup_kernel<<<1, 256>>>((const unsigned*)d_in[idxc[0]], (const unsigned*)d_in[idxc[1]]);
    seed_kernel<<<(NTOK * DDIM + 255) / 256, 256>>>(out);

    lora_t_kernel<false><<<NP, 256>>>(hidden, up_a, DDIM);

    {
        dim3 grid(UPW / BN, (NP + BM - 1) / BM, NEXP);
        mma_gemm<false><<<grid, 256>>>(hidden, w_up, up_b, DDIM, UPW);
    }

    act_kernel<<<(NP * HDIM + 255) / 256, 256>>>();

    lora_t_kernel<true><<<NP, 256>>>(nullptr, down_a, HDIM);

    {
        dim3 grid(DDIM / BN, (NP + BM - 1) / BM, NEXP);
        mma_gemm<true><<<grid, 256>>>(nullptr, w_down, down_b, HDIM, DDIM);
    }

    combine_verdict<<<(NTOK * DDIM + 255) / 256, 256>>>(out);
}

// round 9
// speedup vs baseline: 2.1865x; 1.5580x over previous
#include <cuda_runtime.h>
#include <cuda_bf16.h>
#include <math.h>
#include <stdint.h>

#define NTOK 1024
#define NEXP 16
#define HDIM 1024
#define DDIM 2048
#define RDIM 16
#define NP   2048          // (token, k) pairs
#define UPW  2048          // 2*H
#define SCALE 0.25f

// -------- device scratch: referenced ONLY from device code (GB300/ATS host-shadow trap) --
__device__ int   g_setupdone;
__device__ int   g_bindfail;
__device__ int   g_ids[NP];
__device__ float g_tw[NP];
__device__ int   g_off[NEXP + 1];
__device__ int   g_pairs[NP];
__device__ float g_t[NP * RDIM];
__device__ float g_t2[NP * RDIM];
__device__ float g_up[(size_t)NP * UPW];
__device__ float g_act[(size_t)NP * HDIM];
__device__ float g_down[(size_t)NP * DDIM];

__device__ __forceinline__ unsigned f2tf(float f) {
    unsigned u;
    asm("cvt.rna.tf32.f32 %0, %1;" : "=r"(u) : "f"(f));
    return u;
}

// -------- setup: semantic id/weight identification + expert grouping --------
__global__ __launch_bounds__(256) void setup_kernel(const unsigned* __restrict__ cA,
                                                    const unsigned* __restrict__ cB) {
    __shared__ int wf32[2];
    __shared__ int idu[2], idl[2], idf[2];
    __shared__ int cnt[NEXP], cur[NEXP];
    __shared__ int idsc, idsmode;
    int tid = threadIdx.x;
    if (tid < 2) { wf32[tid] = 0; idu[tid] = 0; idl[tid] = 0; idf[tid] = 0; }
    if (tid < NEXP) cnt[tid] = 0;
    __syncthreads();

    for (int c = 0; c < 2; c++) {
        const unsigned* X = c ? cB : cA;
        int sf = 0, bu = 0, bl = 0, bf = 0;
        for (int t = tid; t < 512; t += 256) {
            unsigned w0 = X[2 * t], w1 = X[2 * t + 1];
            float a = __uint_as_float(w0), b = __uint_as_float(w1);
            if (fabsf(a + b - 1.0f) < 0.02f) sf++;
            if (w0 >= NEXP || w1 >= NEXP) bu = 1;
            if (w0 >= NEXP || w1 != 0) bl = 1;
            if (!(a >= 0.f && a < (float)NEXP && a == floorf(a)) ||
                !(b >= 0.f && b < (float)NEXP && b == floorf(b))) bf = 1;
        }
        atomicAdd(&wf32[c], sf);
        if (bu) atomicExch(&idu[c], 1);
        if (bl) atomicExch(&idl[c], 1);
        if (bf) atomicExch(&idf[c], 1);
    }
    __syncthreads();

    if (tid == 0) {
        int wmode[2], imode[2];
        for (int c = 0; c < 2; c++) {
            wmode[c] = (wf32[c] > 480) ? 1 : 0;
            imode[c] = (!idl[c]) ? 2 : ((!idu[c]) ? 1 : ((!idf[c]) ? 3 : 0));
        }
        int ic = -1;
        if (imode[0] && wmode[1]) ic = 0;
        else if (imode[1] && wmode[0]) ic = 1;
        g_bindfail = (ic < 0) ? 1 : 0;
        idsc = (ic < 0) ? 0 : ic;
        idsmode = imode[idsc] ? imode[idsc] : 1;
    }
    __syncthreads();

    const unsigned* idsbuf = idsc ? cB : cA;
    const unsigned* twbuf  = idsc ? cA : cB;
    int im = idsmode;
    for (int p = tid; p < NP; p += 256) {
        int id;
        if (im == 2)      id = (int)idsbuf[2 * p];
        else if (im == 3) id = (int)__uint_as_float(idsbuf[p]);
        else              id = (int)idsbuf[p];
        g_ids[p] = id & (NEXP - 1);
        g_tw[p] = __uint_as_float(twbuf[p]);
    }
    __syncthreads();

    for (int p = tid; p < NP; p += 256) atomicAdd(&cnt[g_ids[p]], 1);
    __syncthreads();
    if (tid == 0) {
        int a = 0;
        for (int e = 0; e < NEXP; e++) { g_off[e] = a; a += cnt[e]; }
        g_off[NEXP] = a;
    }
    __syncthreads();
    if (tid < NEXP) cur[tid] = g_off[tid];
    __syncthreads();
    for (int p = tid; p < NP; p += 256) {
        int pos = atomicAdd(&cur[g_ids[p]], 1);
        g_pairs[pos & (NP - 1)] = p;
    }
    __syncthreads();
    if (tid == 0) g_setupdone = 1;
}

// -------- seeds (diagnostic sentinels) --------
__global__ __launch_bounds__(256) void seed_kernel(float* __restrict__ outv) {
    int i = blockIdx.x * blockDim.x + threadIdx.x;
    if (i == 0) { g_t[0] = 777.0f; g_t2[0] = 777.0f; }
    if (i < 256) { g_up[i] = 12345.0f; g_down[i] = 0.125f; }
    if (i < NTOK * DDIM) outv[i] = 0.5f;
}

// -------- LoRA-A GEMV (fp32) --------
template <bool DOWN>
__global__ __launch_bounds__(256) void lora_t_kernel(const float* __restrict__ Xv,
                                                     const float* __restrict__ A, int Dlen) {
    int p = blockIdx.x;
    int e = g_ids[p];
    float* T = DOWN ? g_t2 : g_t;
    int warp = threadIdx.x >> 5, lane = threadIdx.x & 31;
    const float* xrow = DOWN ? (g_act + (size_t)p * Dlen)
                             : (Xv + (size_t)(p >> 1) * Dlen);
    for (int r = warp; r < RDIM; r += 8) {
        const float* a = A + ((size_t)e * RDIM + r) * Dlen;
        float s = 0.f;
        for (int i = lane * 4; i < Dlen; i += 128) {
            float4 xv = *(const float4*)(xrow + i);
            float4 av = *(const float4*)(a + i);
            s += xv.x * av.x + xv.y * av.y + xv.z * av.z + xv.w * av.w;
        }
        #pragma unroll
        for (int o = 16; o; o >>= 1) s += __shfl_xor_sync(0xffffffffu, s, o);
        if (lane == 0) T[p * RDIM + r] = s;
    }
}

// ======= expert-grouped tf32 mma.sync GEMM, XOR-swizzled smem, LoRA-B folded =======
// Block tile 128x128x32. 8 warps as 2(M) x 4(N); warp tile 64x32 (mt=4, nt=4).
// Smem: 32 tf32 words/row (128B). chunk-XOR swizzle: word(r,k) = r*32 + ((k>>2 ^ r%8)<<2) + k%4.
//   -> STS.128 stores conflict-free, LDS.32 fragment loads conflict-free.
#define BM 128
#define BN 128
#define BK 32

__device__ __forceinline__ void stsw(unsigned* tile, int r, int kb, float4 v) {
    int idx = r * 32 + ((((kb >> 2) ^ (r & 7)) << 2));
    uint4 u = make_uint4(f2tf(v.x), f2tf(v.y), f2tf(v.z), f2tf(v.w));
    *(uint4*)&tile[idx] = u;
}
__device__ __forceinline__ unsigned ldsw(const unsigned* tile, int r, int k) {
    return tile[r * 32 + (((k >> 2) ^ (r & 7)) << 2) + (k & 3)];
}

template <bool IS_DOWN>
__global__ __launch_bounds__(256) void mma_gemm(const float* __restrict__ Av,   // hidden (up only)
                                                const float* __restrict__ W,    // [E, Ncols, Kd]
                                                const float* __restrict__ LB,   // [E, Ncols, R]
                                                int Kd, int Ncols) {
    int e = blockIdx.z;
    int mstart = g_off[e] + blockIdx.y * BM;
    int mend = g_off[e + 1];
    if (mstart >= mend) return;
    int mv = min(BM, mend - mstart);
    int o0 = blockIdx.x * BN;

    __shared__ __align__(16) unsigned As[BM * 32];
    __shared__ __align__(16) unsigned Bs[BN * 32];
    __shared__ int Pr[BM];

    int tid = threadIdx.x;
    int lane = tid & 31, wid = tid >> 5;
    int warp_m = wid >> 2, warp_n = wid & 3;
    int am_base = warp_m * 64;
    int bn_base = warp_n * 32;

    if (tid < BM) Pr[tid] = g_pairs[mstart + ((tid < mv) ? tid : (mv - 1))];
    __syncthreads();

    // loader: each thread owns one tile row (A and B) and a 16-k half
    int lrow  = tid >> 1;            // 0..127
    int khalf = (tid & 1) * 16;      // 0 or 16

    int prow = Pr[lrow];
    int arow = IS_DOWN ? prow : (prow >> 1);
    const float* abase = (IS_DOWN ? g_act : Av) + (size_t)arow * Kd + khalf;
    const float* bbase = W + ((size_t)e * Ncols + o0 + lrow) * Kd + khalf;

    float c[4][4][4];
    #pragma unroll
    for (int i = 0; i < 4; i++)
        #pragma unroll
        for (int j = 0; j < 4; j++)
            #pragma unroll
            for (int q = 0; q < 4; q++) c[i][j][q] = 0.f;

    float4 av[4], bv[4];
    int nch = Kd / BK;

    // prefetch chunk 0
    #pragma unroll
    for (int j = 0; j < 4; j++) {
        av[j] = *(const float4*)(abase + j * 4);
        bv[j] = *(const float4*)(bbase + j * 4);
    }

    int kl = (lane & 3);             // fragment k within 8-group
    int rquad = lane >> 2;           // fragment row within 8

    for (int ch = 0; ch < nch; ch++) {
        __syncthreads();
        #pragma unroll
        for (int j = 0; j < 4; j++) {
            stsw(As, lrow, khalf + j * 4, av[j]);
            stsw(Bs, lrow, khalf + j * 4, bv[j]);
        }
        __syncthreads();
        if (ch + 1 < nch) {
            const float* ap = abase + (ch + 1) * BK;
            const float* bp = bbase + (ch + 1) * BK;
            #pragma unroll
            for (int j = 0; j < 4; j++) {
                av[j] = *(const float4*)(ap + j * 4);
                bv[j] = *(const float4*)(bp + j * 4);
            }
        }
        #pragma unroll
        for (int ks = 0; ks < 4; ks++) {
            int k0 = ks * 8 + kl;
            unsigned a0[4], a1[4], a2[4], a3[4];
            #pragma unroll
            for (int mt = 0; mt < 4; mt++) {
                int r0 = am_base + mt * 16 + rquad;
                a0[mt] = ldsw(As, r0, k0);
                a1[mt] = ldsw(As, r0 + 8, k0);
                a2[mt] = ldsw(As, r0, k0 + 4);
                a3[mt] = ldsw(As, r0 + 8, k0 + 4);
            }
            #pragma unroll
            for (int nt = 0; nt < 4; nt++) {
                int cn = bn_base + nt * 8 + rquad;
                unsigned b0 = ldsw(Bs, cn, k0);
                unsigned b1 = ldsw(Bs, cn, k0 + 4);
                #pragma unroll
                for (int mt = 0; mt < 4; mt++) {
                    asm volatile(
                        "mma.sync.aligned.m16n8k8.row.col.f32.tf32.tf32.f32 "
                        "{%0,%1,%2,%3}, {%4,%5,%6,%7}, {%8,%9}, {%0,%1,%2,%3};"
                        : "+f"(c[mt][nt][0]), "+f"(c[mt][nt][1]),
                          "+f"(c[mt][nt][2]), "+f"(c[mt][nt][3])
                        : "r"(a0[mt]), "r"(a1[mt]), "r"(a2[mt]), "r"(a3[mt]),
                          "r"(b0), "r"(b1));
                }
            }
        }
    }

    // ---- LoRA-B extension chunk (K=16): A <- SCALE*T[p][r], B <- LB[n][r] ----
    __syncthreads();
    if ((tid & 1) == 0) {
        int row = tid >> 1;
        const float* tp = (IS_DOWN ? g_t2 : g_t) + Pr[row] * RDIM;
        const float* lp = LB + ((size_t)e * Ncols + o0 + row) * RDIM;
        #pragma unroll
        for (int j = 0; j < 4; j++) {
            float4 v = *(const float4*)(tp + j * 4);
            v.x *= SCALE; v.y *= SCALE; v.z *= SCALE; v.w *= SCALE;
            stsw(As, row, j * 4, v);
            stsw(Bs, row, j * 4, *(const float4*)(lp + j * 4));
        }
    }
    __syncthreads();
    #pragma unroll
    for (int ks = 0; ks < 2; ks++) {
        int k0 = ks * 8 + kl;
        unsigned a0[4], a1[4], a2[4], a3[4];
        #pragma unroll
        for (int mt = 0; mt < 4; mt++) {
            int r0 = am_base + mt * 16 + rquad;
            a0[mt] = ldsw(As, r0, k0);
            a1[mt] = ldsw(As, r0 + 8, k0);
            a2[mt] = ldsw(As, r0, k0 + 4);
            a3[mt] = ldsw(As, r0 + 8, k0 + 4);
        }
        #pragma unroll
        for (int nt = 0; nt < 4; nt++) {
            int cn = bn_base + nt * 8 + rquad;
            unsigned b0 = ldsw(Bs, cn, k0);
            unsigned b1 = ldsw(Bs, cn, k0 + 4);
            #pragma unroll
            for (int mt = 0; mt < 4; mt++) {
                asm volatile(
                    "mma.sync.aligned.m16n8k8.row.col.f32.tf32.tf32.f32 "
                    "{%0,%1,%2,%3}, {%4,%5,%6,%7}, {%8,%9}, {%0,%1,%2,%3};"
                    : "+f"(c[mt][nt][0]), "+f"(c[mt][nt][1]),
                      "+f"(c[mt][nt][2]), "+f"(c[mt][nt][3])
                    : "r"(a0[mt]), "r"(a1[mt]), "r"(a2[mt]), "r"(a3[mt]),
                      "r"(b0), "r"(b1));
            }
        }
    }

    // ---- writeout ----
    float* Out = IS_DOWN ? g_down : g_up;
    #pragma unroll
    for (int mt = 0; mt < 4; mt++) {
        int m0 = am_base + mt * 16 + rquad;
        #pragma unroll
        for (int half = 0; half < 2; half++) {
            int m = m0 + half * 8;
            if (m >= mv) continue;
            int p = Pr[m];
            float w = IS_DOWN ? g_tw[p] : 1.0f;
            float* op = Out + (size_t)p * Ncols + o0;
            #pragma unroll
            for (int nt = 0; nt < 4; nt++) {
                int n = bn_base + nt * 8 + (lane & 3) * 2;
                float2 v;
                v.x = c[mt][nt][half * 2 + 0];
                v.y = c[mt][nt][half * 2 + 1];
                if (IS_DOWN) { v.x *= w; v.y *= w; }
                *(float2*)&op[n] = v;
            }
        }
    }
}

// -------- gelu(up[:H]) * up[H:] --------
__global__ __launch_bounds__(256) void act_kernel() {
    int i = blockIdx.x * blockDim.x + threadIdx.x;
    if (i >= NP * HDIM) return;
    int p = i >> 10, h = i & (HDIM - 1);
    float a = g_up[(size_t)p * UPW + h];
    float b = g_up[(size_t)p * UPW + HDIM + h];
    float ge = 0.5f * a * (1.0f + erff(a * 0.70710678118654752f));
    g_act[(size_t)p * HDIM + h] = ge * b;
}

// -------- combine + verdict --------
__global__ __launch_bounds__(256) void combine_verdict(float* __restrict__ outv) {
    int code = 0;
    if (!g_setupdone)               code = 1;
    else if (g_bindfail)            code = 2;
    else if (g_off[NEXP] != NP)     code = 4;
    else if (g_t[0] == 777.0f)      code = 3;
    else if (g_up[0] == 12345.0f)   code = 8;
    else if (g_t2[0] == 777.0f)     code = 5;
    else if (g_down[0] == 0.125f)   code = 16;
    int i = blockIdx.x * blockDim.x + threadIdx.x;
    if (i >= NTOK * DDIM) return;
    float v;
    if (code) v = (float)code;
    else {
        int n = i >> 11, d = i & (DDIM - 1);
        v = g_down[(size_t)(2 * n) * DDIM + d] + g_down[(size_t)(2 * n + 1) * DDIM + d];
    }
    outv[i] = v;
}

extern "C" void kernel_launch(void* const* d_in, const int* in_sizes, int n_in,
                              void* d_out, int out_size) {
    long long mx = 0;
    for (int i = 0; i < n_in; i++) if ((long long)in_sizes[i] > mx) mx = in_sizes[i];
    int div = 1;
    if (mx == 268435456LL) div = 4;
    else if (mx == 134217728LL) div = 2;

    int idx_hidden = -1, idx_wup = -1, idx_wdown = -1, idx_downa = -1;
    int idxc[2] = {-1, -1}; int nc = 0;
    int idx512k[3] = {-1, -1, -1}; int n512k = 0;
    for (int i = 0; i < n_in; i++) {
        long long es = (long long)in_sizes[i] / div;
        if      (es == 2097152)  idx_hidden = i;
        else if (es == 67108864) idx_wup = i;
        else if (es == 33554432) idx_wdown = i;
        else if (es == 262144)   idx_downa = i;
        else if (es == 2048 || (div == 2 && es == 4096)) { if (nc < 2) idxc[nc++] = i; }
        else if (es == 524288)   { if (n512k < 3) idx512k[n512k++] = i; }
    }

    int idx_upa = -1, idx_upb = -1, idx_downb = -1;
    bool ok = (idx_hidden >= 0 && idx_wup >= 0 && idx_wdown >= 0 && idx_downa >= 0 &&
               nc == 2 && n512k == 3);
    if (ok) {
        if (idx_downa < idx512k[0]) { idx_downb = idx512k[0]; idx_upa = idx512k[1]; idx_upb = idx512k[2]; }
        else                        { idx_upa = idx512k[0]; idx_upb = idx512k[1]; idx_downb = idx512k[2]; }
    } else if (n_in >= 9) {
        idx_hidden = 0; idxc[0] = 1; idxc[1] = 2; idx_wup = 3; idx_wdown = 4;
        idx_upa = 5; idx_upb = 6; idx_downa = 7; idx_downb = 8;
    } else {
        return;
    }

    const float* hidden = (const float*)d_in[idx_hidden];
    const float* w_up   = (const float*)d_in[idx_wup];
    const float* w_down = (const float*)d_in[idx_wdown];
    const float* up_a   = (const float*)d_in[idx_upa];
    const float* up_b   = (const float*)d_in[idx_upb];
    const float* down_a = (const float*)d_in[idx_downa];
    const float* down_b = (const float*)d_in[idx_downb];
    float* out = (float*)d_out;

    setup_kernel<<<1, 256>>>((const unsigned*)d_in[idxc[0]], (const unsigned*)d_in[idxc[1]]);
    seed_kernel<<<(NTOK * DDIM + 255) / 256, 256>>>(out);

    lora_t_kernel<false><<<NP, 256>>>(hidden, up_a, DDIM);

    {
        dim3 grid(UPW / BN, (NP + BM - 1) / BM, NEXP);
        mma_gemm<false><<<grid, 256>>>(hidden, w_up, up_b, DDIM, UPW);
    }

    act_kernel<<<(NP * HDIM + 255) / 256, 256>>>();

    lora_t_kernel<true><<<NP, 256>>>(nullptr, down_a, HDIM);

    {
        dim3 grid(DDIM / BN, (NP + BM - 1) / BM, NEXP);
        mma_gemm<true><<<grid, 256>>>(nullptr, w_down, down_b, HDIM, DDIM);
    }

    combine_verdict<<<(NTOK * DDIM + 255) / 256, 256>>>(out);
}

// round 10
// speedup vs baseline: 2.3831x; 1.0899x over previous
#include <cuda_runtime.h>
#include <cuda_bf16.h>
#include <math.h>
#include <stdint.h>

#define NTOK 1024
#define NEXP 16
#define HDIM 1024
#define DDIM 2048
#define RDIM 16
#define NP   2048          // (token, k) pairs
#define UPW  2048          // 2*H
#define SCALE 0.25f

// -------- device scratch: referenced ONLY from device code (GB300/ATS host-shadow trap) --
__device__ int   g_setupdone;
__device__ int   g_bindfail;
__device__ int   g_ids[NP];
__device__ float g_tw[NP];
__device__ int   g_off[NEXP + 1];
__device__ int   g_pairs[NP];
__device__ float g_t[NP * RDIM];
__device__ float g_t2[NP * RDIM];
__device__ __align__(16) float g_up[(size_t)NP * UPW];
__device__ __align__(16) float g_act[(size_t)NP * HDIM];
__device__ __align__(16) float g_down[(size_t)NP * DDIM];

__device__ __forceinline__ unsigned f2tf(float f) {
    unsigned u;
    asm("cvt.rna.tf32.f32 %0, %1;" : "=r"(u) : "f"(f));
    return u;
}
__device__ __forceinline__ unsigned u2tf(unsigned x) { return f2tf(__uint_as_float(x)); }
__device__ __forceinline__ uint32_t smem_u32(const void* p) {
    uint32_t a;
    asm("{ .reg .u64 t; cvta.to.shared.u64 t, %1; cvt.u32.u64 %0, t; }" : "=r"(a) : "l"(p));
    return a;
}
#define CP_COMMIT() asm volatile("cp.async.commit_group;" ::: "memory")
#define CP_WAIT1()  asm volatile("cp.async.wait_group 1;" ::: "memory")
#define CP_WAIT0()  asm volatile("cp.async.wait_group 0;" ::: "memory")

// -------- setup: semantic id/weight identification + expert grouping --------
__global__ __launch_bounds__(256) void setup_kernel(const unsigned* __restrict__ cA,
                                                    const unsigned* __restrict__ cB) {
    __shared__ int wf32[2];
    __shared__ int idu[2], idl[2], idf[2];
    __shared__ int cnt[NEXP], cur[NEXP];
    __shared__ int idsc, idsmode;
    int tid = threadIdx.x;
    if (tid < 2) { wf32[tid] = 0; idu[tid] = 0; idl[tid] = 0; idf[tid] = 0; }
    if (tid < NEXP) cnt[tid] = 0;
    __syncthreads();

    for (int c = 0; c < 2; c++) {
        const unsigned* X = c ? cB : cA;
        int sf = 0, bu = 0, bl = 0, bf = 0;
        for (int t = tid; t < 512; t += 256) {
            unsigned w0 = X[2 * t], w1 = X[2 * t + 1];
            float a = __uint_as_float(w0), b = __uint_as_float(w1);
            if (fabsf(a + b - 1.0f) < 0.02f) sf++;
            if (w0 >= NEXP || w1 >= NEXP) bu = 1;
            if (w0 >= NEXP || w1 != 0) bl = 1;
            if (!(a >= 0.f && a < (float)NEXP && a == floorf(a)) ||
                !(b >= 0.f && b < (float)NEXP && b == floorf(b))) bf = 1;
        }
        atomicAdd(&wf32[c], sf);
        if (bu) atomicExch(&idu[c], 1);
        if (bl) atomicExch(&idl[c], 1);
        if (bf) atomicExch(&idf[c], 1);
    }
    __syncthreads();

    if (tid == 0) {
        int wmode[2], imode[2];
        for (int c = 0; c < 2; c++) {
            wmode[c] = (wf32[c] > 480) ? 1 : 0;
            imode[c] = (!idl[c]) ? 2 : ((!idu[c]) ? 1 : ((!idf[c]) ? 3 : 0));
        }
        int ic = -1;
        if (imode[0] && wmode[1]) ic = 0;
        else if (imode[1] && wmode[0]) ic = 1;
        g_bindfail = (ic < 0) ? 1 : 0;
        idsc = (ic < 0) ? 0 : ic;
        idsmode = imode[idsc] ? imode[idsc] : 1;
    }
    __syncthreads();

    const unsigned* idsbuf = idsc ? cB : cA;
    const unsigned* twbuf  = idsc ? cA : cB;
    int im = idsmode;
    for (int p = tid; p < NP; p += 256) {
        int id;
        if (im == 2)      id = (int)idsbuf[2 * p];
        else if (im == 3) id = (int)__uint_as_float(idsbuf[p]);
        else              id = (int)idsbuf[p];
        g_ids[p] = id & (NEXP - 1);
        g_tw[p] = __uint_as_float(twbuf[p]);
    }
    __syncthreads();

    for (int p = tid; p < NP; p += 256) atomicAdd(&cnt[g_ids[p]], 1);
    __syncthreads();
    if (tid == 0) {
        int a = 0;
        for (int e = 0; e < NEXP; e++) { g_off[e] = a; a += cnt[e]; }
        g_off[NEXP] = a;
    }
    __syncthreads();
    if (tid < NEXP) cur[tid] = g_off[tid];
    __syncthreads();
    for (int p = tid; p < NP; p += 256) {
        int pos = atomicAdd(&cur[g_ids[p]], 1);
        g_pairs[pos & (NP - 1)] = p;
    }
    __syncthreads();
    if (tid == 0) g_setupdone = 1;
}

// -------- seeds (diagnostic sentinels) --------
__global__ __launch_bounds__(256) void seed_kernel(float* __restrict__ outv) {
    int i = blockIdx.x * blockDim.x + threadIdx.x;
    if (i == 0) { g_t[0] = 777.0f; g_t2[0] = 777.0f; }
    if (i < 256) { g_up[i] = 12345.0f; g_down[i] = 0.125f; }
    if (i < NTOK * DDIM) outv[i] = 0.5f;
}

// -------- LoRA-A GEMV (fp32) --------
template <bool DOWN>
__global__ __launch_bounds__(256) void lora_t_kernel(const float* __restrict__ Xv,
                                                     const float* __restrict__ A, int Dlen) {
    int p = blockIdx.x;
    int e = g_ids[p];
    float* T = DOWN ? g_t2 : g_t;
    int warp = threadIdx.x >> 5, lane = threadIdx.x & 31;
    const float* xrow = DOWN ? (g_act + (size_t)p * Dlen)
                             : (Xv + (size_t)(p >> 1) * Dlen);
    for (int r = warp; r < RDIM; r += 8) {
        const float* a = A + ((size_t)e * RDIM + r) * Dlen;
        float s = 0.f;
        for (int i = lane * 4; i < Dlen; i += 128) {
            float4 xv = *(const float4*)(xrow + i);
            float4 av = *(const float4*)(a + i);
            s += xv.x * av.x + xv.y * av.y + xv.z * av.z + xv.w * av.w;
        }
        #pragma unroll
        for (int o = 16; o; o >>= 1) s += __shfl_xor_sync(0xffffffffu, s, o);
        if (lane == 0) T[p * RDIM + r] = s;
    }
}

// ======= expert-grouped tf32 GEMM: cp.async 3-stage pipeline, XOR swizzle, LoRA folded =======
// Block tile 128x128x32. 8 warps = 2(M) x 4(N), warp tile 64x32.
// Smem word(r,k) = r*32 + ((k>>2 ^ r%8)<<2) + k%4  (16B-granular -> cp.async friendly).
// fp32 lands raw in smem; rna tf32 conversion happens in the fragment load.
#define BM 128
#define BN 128
#define BK 32
#define STW (128 * 32)          // words per stage per operand
#define PIPE_SMEM (3 * STW * 4 * 2 + 512)

__device__ __forceinline__ void stsw(unsigned* tile, int r, int kb, float4 v) {
    int idx = r * 32 + ((((kb >> 2) ^ (r & 7)) << 2));
    uint4 u = make_uint4(f2tf(v.x), f2tf(v.y), f2tf(v.z), f2tf(v.w));
    *(uint4*)&tile[idx] = u;
}
__device__ __forceinline__ unsigned ldsw(const unsigned* tile, int r, int k) {
    return tile[r * 32 + (((k >> 2) ^ (r & 7)) << 2) + (k & 3)];
}
__device__ __forceinline__ void cp16(uint32_t dst, const float* src) {
    asm volatile("cp.async.cg.shared.global [%0], [%1], 16;" :: "r"(dst), "l"(src));
}
// issue one 32-k chunk: this thread owns row `lrow`, k-half `khalf` of both tiles
__device__ __forceinline__ void issue_chunk(uint32_t a_s, uint32_t b_s,
                                            const float* ap, const float* bp,
                                            int lrow, int khalf) {
    int rx = (lrow & 7);
    #pragma unroll
    for (int j = 0; j < 4; j++) {
        int kc = (khalf >> 2) + j;
        uint32_t off = (uint32_t)(lrow * 32 + ((kc ^ rx) << 2)) * 4u;
        cp16(a_s + off, ap + j * 4);
        cp16(b_s + off, bp + j * 4);
    }
}
// one 8k-group MMA sweep over nks groups
__device__ __forceinline__ void frag_mma(const unsigned* As, const unsigned* Bs,
                                         int am_base, int bn_base, int kl, int rquad,
                                         int nks, float c[4][4][4]) {
    for (int ks = 0; ks < nks; ks++) {
        int k0 = ks * 8 + kl;
        unsigned a0[4], a1[4], a2[4], a3[4];
        #pragma unroll
        for (int mt = 0; mt < 4; mt++) {
            int r0 = am_base + mt * 16 + rquad;
            a0[mt] = u2tf(ldsw(As, r0, k0));
            a1[mt] = u2tf(ldsw(As, r0 + 8, k0));
            a2[mt] = u2tf(ldsw(As, r0, k0 + 4));
            a3[mt] = u2tf(ldsw(As, r0 + 8, k0 + 4));
        }
        #pragma unroll
        for (int nt = 0; nt < 4; nt++) {
            int cn = bn_base + nt * 8 + rquad;
            unsigned b0 = u2tf(ldsw(Bs, cn, k0));
            unsigned b1 = u2tf(ldsw(Bs, cn, k0 + 4));
            #pragma unroll
            for (int mt = 0; mt < 4; mt++) {
                asm volatile(
                    "mma.sync.aligned.m16n8k8.row.col.f32.tf32.tf32.f32 "
                    "{%0,%1,%2,%3}, {%4,%5,%6,%7}, {%8,%9}, {%0,%1,%2,%3};"
                    : "+f"(c[mt][nt][0]), "+f"(c[mt][nt][1]),
                      "+f"(c[mt][nt][2]), "+f"(c[mt][nt][3])
                    : "r"(a0[mt]), "r"(a1[mt]), "r"(a2[mt]), "r"(a3[mt]),
                      "r"(b0), "r"(b1));
            }
        }
    }
}

template <bool IS_DOWN>
__global__ __launch_bounds__(256) void mma_gemm(const float* __restrict__ Av,   // hidden (up only)
                                                const float* __restrict__ W,    // [E, Ncols, Kd]
                                                const float* __restrict__ LB,   // [E, Ncols, R]
                                                int Kd, int Ncols) {
    int e = blockIdx.z;
    int mstart = g_off[e] + blockIdx.y * BM;
    int mend = g_off[e + 1];
    if (mstart >= mend) return;
    int mv = min(BM, mend - mstart);
    int o0 = blockIdx.x * BN;

    extern __shared__ __align__(16) unsigned dynsmem[];
    unsigned* Abuf = dynsmem;                    // 3 stages x 4096 words
    unsigned* Bbuf = dynsmem + 3 * STW;
    int* Pr = (int*)(dynsmem + 6 * STW);

    int tid = threadIdx.x;
    int lane = tid & 31, wid = tid >> 5;
    int warp_m = wid >> 2, warp_n = wid & 3;
    int am_base = warp_m * 64;
    int bn_base = warp_n * 32;

    if (tid < BM) Pr[tid] = g_pairs[mstart + ((tid < mv) ? tid : (mv - 1))];
    __syncthreads();

    int lrow  = tid >> 1;            // 0..127
    int khalf = (tid & 1) * 16;      // 0 or 16

    int prow = Pr[lrow];
    int arow = IS_DOWN ? prow : (prow >> 1);
    const float* abase = (IS_DOWN ? g_act : Av) + (size_t)arow * Kd + khalf;
    const float* bbase = W + ((size_t)e * Ncols + o0 + lrow) * Kd + khalf;

    uint32_t a_s0 = smem_u32(Abuf), b_s0 = smem_u32(Bbuf);

    float c[4][4][4];
    #pragma unroll
    for (int i = 0; i < 4; i++)
        #pragma unroll
        for (int j = 0; j < 4; j++)
            #pragma unroll
            for (int q = 0; q < 4; q++) c[i][j][q] = 0.f;

    int nch = Kd / BK;
    int kl = (lane & 3);
    int rquad = lane >> 2;

    // prologue: stage chunks 0,1
    issue_chunk(a_s0, b_s0, abase, bbase, lrow, khalf);
    CP_COMMIT();
    if (nch > 1) issue_chunk(a_s0 + STW * 4, b_s0 + STW * 4, abase + BK, bbase + BK, lrow, khalf);
    CP_COMMIT();

    for (int ch = 0; ch < nch; ch++) {
        CP_WAIT1();
        __syncthreads();
        int nx = ch + 2;
        if (nx < nch) {
            int st = nx - (nx / 3) * 3;
            issue_chunk(a_s0 + st * STW * 4, b_s0 + st * STW * 4,
                        abase + nx * BK, bbase + nx * BK, lrow, khalf);
        }
        CP_COMMIT();
        int st = ch - (ch / 3) * 3;
        frag_mma(Abuf + st * STW, Bbuf + st * STW, am_base, bn_base, kl, rquad, 4, c);
    }

    // ---- LoRA-B extension chunk (K=16): A <- SCALE*T[p][r], B <- LB[n][r] ----
    CP_WAIT0();
    __syncthreads();
    if ((tid & 1) == 0) {
        int row = tid >> 1;
        const float* tp = (IS_DOWN ? g_t2 : g_t) + Pr[row] * RDIM;
        const float* lp = LB + ((size_t)e * Ncols + o0 + row) * RDIM;
        #pragma unroll
        for (int j = 0; j < 4; j++) {
            float4 v = *(const float4*)(tp + j * 4);
            v.x *= SCALE; v.y *= SCALE; v.z *= SCALE; v.w *= SCALE;
            stsw(Abuf, row, j * 4, v);
            stsw(Bbuf, row, j * 4, *(const float4*)(lp + j * 4));
        }
    }
    __syncthreads();
    frag_mma(Abuf, Bbuf, am_base, bn_base, kl, rquad, 2, c);

    // ---- writeout ----
    float* Out = IS_DOWN ? g_down : g_up;
    #pragma unroll
    for (int mt = 0; mt < 4; mt++) {
        int m0 = am_base + mt * 16 + rquad;
        #pragma unroll
        for (int half = 0; half < 2; half++) {
            int m = m0 + half * 8;
            if (m >= mv) continue;
            int p = Pr[m];
            float w = IS_DOWN ? g_tw[p] : 1.0f;
            float* op = Out + (size_t)p * Ncols + o0;
            #pragma unroll
            for (int nt = 0; nt < 4; nt++) {
                int n = bn_base + nt * 8 + (lane & 3) * 2;
                float2 v;
                v.x = c[mt][nt][half * 2 + 0];
                v.y = c[mt][nt][half * 2 + 1];
                if (IS_DOWN) { v.x *= w; v.y *= w; }
                *(float2*)&op[n] = v;
            }
        }
    }
}

// -------- gelu(up[:H]) * up[H:] --------
__global__ __launch_bounds__(256) void act_kernel() {
    int i = blockIdx.x * blockDim.x + threadIdx.x;
    if (i >= NP * HDIM) return;
    int p = i >> 10, h = i & (HDIM - 1);
    float a = g_up[(size_t)p * UPW + h];
    float b = g_up[(size_t)p * UPW + HDIM + h];
    float ge = 0.5f * a * (1.0f + erff(a * 0.70710678118654752f));
    g_act[(size_t)p * HDIM + h] = ge * b;
}

// -------- combine + verdict --------
__global__ __launch_bounds__(256) void combine_verdict(float* __restrict__ outv) {
    int code = 0;
    if (!g_setupdone)               code = 1;
    else if (g_bindfail)            code = 2;
    else if (g_off[NEXP] != NP)     code = 4;
    else if (g_t[0] == 777.0f)      code = 3;
    else if (g_up[0] == 12345.0f)   code = 8;
    else if (g_t2[0] == 777.0f)     code = 5;
    else if (g_down[0] == 0.125f)   code = 16;
    int i = blockIdx.x * blockDim.x + threadIdx.x;
    if (i >= NTOK * DDIM) return;
    float v;
    if (code) v = (float)code;
    else {
        int n = i >> 11, d = i & (DDIM - 1);
        v = g_down[(size_t)(2 * n) * DDIM + d] + g_down[(size_t)(2 * n + 1) * DDIM + d];
    }
    outv[i] = v;
}

extern "C" void kernel_launch(void* const* d_in, const int* in_sizes, int n_in,
                              void* d_out, int out_size) {
    long long mx = 0;
    for (int i = 0; i < n_in; i++) if ((long long)in_sizes[i] > mx) mx = in_sizes[i];
    int div = 1;
    if (mx == 268435456LL) div = 4;
    else if (mx == 134217728LL) div = 2;

    int idx_hidden = -1, idx_wup = -1, idx_wdown = -1, idx_downa = -1;
    int idxc[2] = {-1, -1}; int nc = 0;
    int idx512k[3] = {-1, -1, -1}; int n512k = 0;
    for (int i = 0; i < n_in; i++) {
        long long es = (long long)in_sizes[i] / div;
        if      (es == 2097152)  idx_hidden = i;
        else if (es == 67108864) idx_wup = i;
        else if (es == 33554432) idx_wdown = i;
        else if (es == 262144)   idx_downa = i;
        else if (es == 2048 || (div == 2 && es == 4096)) { if (nc < 2) idxc[nc++] = i; }
        else if (es == 524288)   { if (n512k < 3) idx512k[n512k++] = i; }
    }

    int idx_upa = -1, idx_upb = -1, idx_downb = -1;
    bool ok = (idx_hidden >= 0 && idx_wup >= 0 && idx_wdown >= 0 && idx_downa >= 0 &&
               nc == 2 && n512k == 3);
    if (ok) {
        if (idx_downa < idx512k[0]) { idx_downb = idx512k[0]; idx_upa = idx512k[1]; idx_upb = idx512k[2]; }
        else                        { idx_upa = idx512k[0]; idx_upb = idx512k[1]; idx_downb = idx512k[2]; }
    } else if (n_in >= 9) {
        idx_hidden = 0; idxc[0] = 1; idxc[1] = 2; idx_wup = 3; idx_wdown = 4;
        idx_upa = 5; idx_upb = 6; idx_downa = 7; idx_downb = 8;
    } else {
        return;
    }

    const float* hidden = (const float*)d_in[idx_hidden];
    const float* w_up   = (const float*)d_in[idx_wup];
    const float* w_down = (const float*)d_in[idx_wdown];
    const float* up_a   = (const float*)d_in[idx_upa];
    const float* up_b   = (const float*)d_in[idx_upb];
    const float* down_a = (const float*)d_in[idx_downa];
    const float* down_b = (const float*)d_in[idx_downb];
    float* out = (float*)d_out;

    static int smem_set = 0;
    if (!smem_set) {
        cudaFuncSetAttribute(mma_gemm<false>, cudaFuncAttributeMaxDynamicSharedMemorySize, PIPE_SMEM);
        cudaFuncSetAttribute(mma_gemm<true>,  cudaFuncAttributeMaxDynamicSharedMemorySize, PIPE_SMEM);
        smem_set = 1;
    }

    setup_kernel<<<1, 256>>>((const unsigned*)d_in[idxc[0]], (const unsigned*)d_in[idxc[1]]);
    seed_kernel<<<(NTOK * DDIM + 255) / 256, 256>>>(out);

    lora_t_kernel<false><<<NP, 256>>>(hidden, up_a, DDIM);

    {
        dim3 grid(UPW / BN, (NP + BM - 1) / BM, NEXP);
        mma_gemm<false><<<grid, 256, PIPE_SMEM>>>(hidden, w_up, up_b, DDIM, UPW);
    }

    act_kernel<<<(NP * HDIM + 255) / 256, 256>>>();

    lora_t_kernel<true><<<NP, 256>>>(nullptr, down_a, HDIM);

    {
        dim3 grid(DDIM / BN, (NP + BM - 1) / BM, NEXP);
        mma_gemm<true><<<grid, 256, PIPE_SMEM>>>(nullptr, w_down, down_b, HDIM, DDIM);
    }

    combine_verdict<<<(NTOK * DDIM + 255) / 256, 256>>>(out);
}